// round 3
// baseline (speedup 1.0000x reference)
#include <cuda_runtime.h>
#include <math.h>

#define N_ROWS 16384
#define DIM 256
#define DT_F 0.01f

// scratch for xi (clipped), passed from MLP kernel to scan kernel
__device__ float g_xi[N_ROWS];

// ---------------------------------------------------------------------------
// Fused MLP kernel: 128 rows per block, 512 threads.
// Stage1: H = relu(X_ @ W1 + b1)         (K=257: 256 from data + omega col)
// Stage2: H = relu(H @ W2 + b2)
// Stage3: H = [relu(H@Wm1+bm1) | relu(H@Wl1+bl1)]   (two 128-wide heads)
// Stage4: per-row dots with Wm2/Wl2 -> xi_mean (softplus), lnvar, xi
// One 128x256 smem buffer holds activations; B slices streamed via smem.
// ---------------------------------------------------------------------------
#define ROWS 128
#define BK   16
#define MLP_SMEM ((ROWS*DIM + ROWS*BK + BK*DIM) * 4)

extern __shared__ float smem[];

__global__ __launch_bounds__(512, 1)
void mlp_kernel(const float* __restrict__ data,
                const float* __restrict__ omega,
                const float* __restrict__ eps,
                const float* __restrict__ W1,  const float* __restrict__ b1,
                const float* __restrict__ W2,  const float* __restrict__ b2,
                const float* __restrict__ Wm1, const float* __restrict__ bm1,
                const float* __restrict__ Wm2, const float* __restrict__ bm2,
                const float* __restrict__ Wl1, const float* __restrict__ bl1,
                const float* __restrict__ Wl2, const float* __restrict__ bl2,
                float* __restrict__ out)
{
    float* Hs = smem;                       // 128 x 256
    float* Xs = smem + ROWS * DIM;          // 128 x 16
    float* Ws = Xs + ROWS * BK;             // 16 x 256

    const int tid = threadIdx.x;
    const int tc  = tid & 31;               // column lane (0..31)
    const int tr  = tid >> 5;               // warp id = row group (0..15)
    const int row0 = blockIdx.x * ROWS;

    float acc[8][8];

    // ===================== Stage 1 =====================
    #pragma unroll
    for (int i = 0; i < 8; i++)
        #pragma unroll
        for (int j = 0; j < 8; j++) acc[i][j] = 0.f;

    for (int k0 = 0; k0 < 256; k0 += BK) {
        // load X slice [128 x 16]
        {
            int r = tid >> 2, q = tid & 3;
            float4 v = *(const float4*)&data[(size_t)(row0 + r) * DIM + k0 + q * 4];
            *(float4*)&Xs[r * BK + q * 4] = v;
        }
        // load W1 slice [16 x 256]
        #pragma unroll
        for (int u = 0; u < 2; u++) {
            int idx = tid + u * 512;        // float4 index (0..1023)
            int kk  = idx >> 6;
            int c4  = (idx & 63) * 4;
            *(float4*)&Ws[kk * DIM + c4] =
                *(const float4*)&W1[(size_t)(k0 + kk) * DIM + c4];
        }
        __syncthreads();
        #pragma unroll
        for (int kk = 0; kk < BK; kk++) {
            float a[8], b[8];
            #pragma unroll
            for (int i = 0; i < 8; i++) a[i] = Xs[(tr * 8 + i) * BK + kk];
            #pragma unroll
            for (int j = 0; j < 8; j++) b[j] = Ws[kk * DIM + tc + 32 * j];
            #pragma unroll
            for (int i = 0; i < 8; i++)
                #pragma unroll
                for (int j = 0; j < 8; j++)
                    acc[i][j] = fmaf(a[i], b[j], acc[i][j]);
        }
        __syncthreads();
    }
    // omega column (k = 256), bias, relu -> Hs
    {
        float aom[8], bom[8], bb[8];
        #pragma unroll
        for (int i = 0; i < 8; i++) aom[i] = omega[row0 + tr * 8 + i];
        #pragma unroll
        for (int j = 0; j < 8; j++) {
            bom[j] = W1[(size_t)256 * DIM + tc + 32 * j];
            bb[j]  = b1[tc + 32 * j];
        }
        #pragma unroll
        for (int i = 0; i < 8; i++)
            #pragma unroll
            for (int j = 0; j < 8; j++)
                Hs[(tr * 8 + i) * DIM + tc + 32 * j] =
                    fmaxf(fmaf(aom[i], bom[j], acc[i][j]) + bb[j], 0.f);
    }
    __syncthreads();

    // ===================== Stage 2 =====================
    #pragma unroll
    for (int i = 0; i < 8; i++)
        #pragma unroll
        for (int j = 0; j < 8; j++) acc[i][j] = 0.f;

    for (int k0 = 0; k0 < 256; k0 += BK) {
        #pragma unroll
        for (int u = 0; u < 2; u++) {
            int idx = tid + u * 512;
            int kk  = idx >> 6;
            int c4  = (idx & 63) * 4;
            *(float4*)&Ws[kk * DIM + c4] =
                *(const float4*)&W2[(size_t)(k0 + kk) * DIM + c4];
        }
        __syncthreads();
        #pragma unroll
        for (int kk = 0; kk < BK; kk++) {
            float a[8], b[8];
            #pragma unroll
            for (int i = 0; i < 8; i++) a[i] = Hs[(tr * 8 + i) * DIM + k0 + kk];
            #pragma unroll
            for (int j = 0; j < 8; j++) b[j] = Ws[kk * DIM + tc + 32 * j];
            #pragma unroll
            for (int i = 0; i < 8; i++)
                #pragma unroll
                for (int j = 0; j < 8; j++)
                    acc[i][j] = fmaf(a[i], b[j], acc[i][j]);
        }
        __syncthreads();
    }
    {
        float bb[8];
        #pragma unroll
        for (int j = 0; j < 8; j++) bb[j] = b2[tc + 32 * j];
        #pragma unroll
        for (int i = 0; i < 8; i++)
            #pragma unroll
            for (int j = 0; j < 8; j++)
                Hs[(tr * 8 + i) * DIM + tc + 32 * j] =
                    fmaxf(acc[i][j] + bb[j], 0.f);
    }
    __syncthreads();

    // ===================== Stage 3 (two heads, 128 cols each) ==============
    #pragma unroll
    for (int i = 0; i < 8; i++)
        #pragma unroll
        for (int j = 0; j < 8; j++) acc[i][j] = 0.f;

    for (int k0 = 0; k0 < 256; k0 += BK) {
        #pragma unroll
        for (int u = 0; u < 2; u++) {
            int idx = tid + u * 512;
            int kk  = idx >> 6;
            int c4  = (idx & 63) * 4;
            const float* src = (c4 < 128)
                ? &Wm1[(size_t)(k0 + kk) * 128 + c4]
                : &Wl1[(size_t)(k0 + kk) * 128 + (c4 - 128)];
            *(float4*)&Ws[kk * DIM + c4] = *(const float4*)src;
        }
        __syncthreads();
        #pragma unroll
        for (int kk = 0; kk < BK; kk++) {
            float a[8], b[8];
            #pragma unroll
            for (int i = 0; i < 8; i++) a[i] = Hs[(tr * 8 + i) * DIM + k0 + kk];
            #pragma unroll
            for (int j = 0; j < 8; j++) b[j] = Ws[kk * DIM + tc + 32 * j];
            #pragma unroll
            for (int i = 0; i < 8; i++)
                #pragma unroll
                for (int j = 0; j < 8; j++)
                    acc[i][j] = fmaf(a[i], b[j], acc[i][j]);
        }
        __syncthreads();
    }
    {
        float bb[8];
        #pragma unroll
        for (int j = 0; j < 8; j++) {
            int c = tc + 32 * j;
            bb[j] = (j < 4) ? bm1[c] : bl1[c - 128];
        }
        #pragma unroll
        for (int i = 0; i < 8; i++)
            #pragma unroll
            for (int j = 0; j < 8; j++)
                Hs[(tr * 8 + i) * DIM + tc + 32 * j] =
                    fmaxf(acc[i][j] + bb[j], 0.f);
    }
    __syncthreads();

    // ===================== Stage 4: head reductions ========================
    // warp tr handles rows tr*8 .. tr*8+7; lanes split the 128-dot 4-way
    const float bm2v = bm2[0];
    const float bl2v = bl2[0];
    #pragma unroll 1
    for (int q = 0; q < 8; q++) {
        int r = tr * 8 + q;
        float s1 = 0.f, s2 = 0.f;
        #pragma unroll
        for (int m = 0; m < 4; m++) {
            int h = tc + 32 * m;
            s1 = fmaf(Hs[r * DIM + h],       __ldg(&Wm2[h]), s1);
            s2 = fmaf(Hs[r * DIM + 128 + h], __ldg(&Wl2[h]), s2);
        }
        #pragma unroll
        for (int o = 16; o > 0; o >>= 1) {
            s1 += __shfl_xor_sync(0xffffffffu, s1, o);
            s2 += __shfl_xor_sync(0xffffffffu, s2, o);
        }
        if (tc == 0) {
            int gr = row0 + r;
            float pm = s1 + bm2v;
            float lv = s2 + bl2v;
            // softplus(pm) = max(pm,0) + log1p(exp(-|pm|))
            float xm = fmaxf(pm, 0.f) + log1pf(expf(-fabsf(pm)));
            float xi = xm + expf(0.5f * lv) * eps[gr];
            xi = fminf(fmaxf(xi, 0.f), 1.f);
            out[gr]            = xm;   // xi_mean
            out[N_ROWS + gr]   = lv;   // xi_lnvar
            g_xi[gr]           = xi;
        }
    }
}

// ---------------------------------------------------------------------------
// Scan kernel: one thread per row. Per-row constants c_j = omega*Wa1[0,j]+b_j
// live in registers (64). Shared w_j = Wa1[1,j], v_j = Wa2[j] via broadcast
// LDS. y values for 32 steps staged in smem, flushed as coalesced row tiles.
// ---------------------------------------------------------------------------
__global__ __launch_bounds__(128, 8)
void scan_kernel(const float* __restrict__ data,
                 const float* __restrict__ omega,
                 const float* __restrict__ Wa1, const float* __restrict__ ba1,
                 const float* __restrict__ Wa2, const float* __restrict__ ba2,
                 float* __restrict__ out)
{
    __shared__ float wv[128];          // [0..63] = w_j, [64..127] = v_j
    __shared__ float ytile[128][33];   // +1 pad: conflict-free both phases

    const int tid = threadIdx.x;
    const int row = blockIdx.x * 128 + tid;

    if (tid < 64) {
        wv[tid]      = Wa1[64 + tid];  // W_aux1[1, j]
        wv[64 + tid] = Wa2[tid];       // W_aux2[j]
    }

    const float om = omega[row];
    float c[64];
    #pragma unroll
    for (int j = 0; j < 64; j++) c[j] = fmaf(om, Wa1[j], ba1[j]);

    const float b2v = ba2[0];
    float y  = data[(size_t)row * DIM]; // init_y = data[:,0]
    float vv = 0.f;
    const float xi = g_xi[row];         // in [0,1]
    const float dm = __expf(-xi * DT_F);
    float f = 1.f;

    float* __restrict__ xout = out + 2 * N_ROWS;
    __syncthreads();

    for (int t = 0; t < 256; t++) {
        ytile[tid][t & 31] = f * y;     // x_PAB[row,t] = exp(-xi*DT*t)*y_t

        float a0 = 0.f, a1 = 0.f, a2 = 0.f, a3 = 0.f;
        #pragma unroll
        for (int j = 0; j < 64; j += 4) {
            a0 = fmaf(fmaxf(fmaf(y, wv[j],     c[j]),     0.f), wv[64 + j],     a0);
            a1 = fmaf(fmaxf(fmaf(y, wv[j + 1], c[j + 1]), 0.f), wv[64 + j + 1], a1);
            a2 = fmaf(fmaxf(fmaf(y, wv[j + 2], c[j + 2]), 0.f), wv[64 + j + 2], a2);
            a3 = fmaf(fmaxf(fmaf(y, wv[j + 3], c[j + 3]), 0.f), wv[64 + j + 3], a3);
        }
        float acc = ((a0 + a1) + (a2 + a3)) + b2v;

        float ynew = fmaf(DT_F, vv, y);   // y += DT * v   (old v)
        vv = fmaf(DT_F, acc, vv);         // v += DT * acc (acc from old y)
        y = ynew;
        f *= dm;

        if ((t & 31) == 31) {
            __syncthreads();
            int tb = t - 31;
            #pragma unroll
            for (int i = 0; i < 32; i++) {
                int idx = i * 128 + tid;
                int rr  = idx >> 5;       // constant per warp
                int cc  = idx & 31;       // = lane
                xout[(size_t)(blockIdx.x * 128 + rr) * DIM + tb + cc] = ytile[rr][cc];
            }
            __syncthreads();
        }
    }
}

// ---------------------------------------------------------------------------
extern "C" void kernel_launch(void* const* d_in, const int* in_sizes, int n_in,
                              void* d_out, int out_size)
{
    const float* data = (const float*)d_in[0];
    const float* omega= (const float*)d_in[1];
    const float* eps  = (const float*)d_in[2];
    const float* W1   = (const float*)d_in[3];  const float* b1  = (const float*)d_in[4];
    const float* W2   = (const float*)d_in[5];  const float* b2  = (const float*)d_in[6];
    const float* Wm1  = (const float*)d_in[7];  const float* bm1 = (const float*)d_in[8];
    const float* Wm2  = (const float*)d_in[9];  const float* bm2 = (const float*)d_in[10];
    const float* Wl1  = (const float*)d_in[11]; const float* bl1 = (const float*)d_in[12];
    const float* Wl2  = (const float*)d_in[13]; const float* bl2 = (const float*)d_in[14];
    const float* Wa1  = (const float*)d_in[15]; const float* ba1 = (const float*)d_in[16];
    const float* Wa2  = (const float*)d_in[17]; const float* ba2 = (const float*)d_in[18];
    float* out = (float*)d_out;

    cudaFuncSetAttribute(mlp_kernel,
                         cudaFuncAttributeMaxDynamicSharedMemorySize, MLP_SMEM);

    mlp_kernel<<<N_ROWS / ROWS, 512, MLP_SMEM>>>(
        data, omega, eps, W1, b1, W2, b2,
        Wm1, bm1, Wm2, bm2, Wl1, bl1, Wl2, bl2, out);

    scan_kernel<<<N_ROWS / 128, 128>>>(data, omega, Wa1, ba1, Wa2, ba2, out);
}

// round 5
// speedup vs baseline: 1.4008x; 1.4008x over previous
#include <cuda_runtime.h>
#include <math.h>

#define N_ROWS 16384
#define DIM 256
#define DT_F 0.01f

// scratch for xi (clipped), passed from MLP kernel to scan kernel
__device__ float g_xi[N_ROWS];

// ---------------------------------------------------------------------------
// Fused MLP kernel: 128 rows per block, 512 threads. (unchanged from R3 —
// measured at the fp32 SIMT FFMA roofline; tensor-core port is a later round)
// ---------------------------------------------------------------------------
#define ROWS 128
#define BK   16
#define MLP_SMEM ((ROWS*DIM + ROWS*BK + BK*DIM) * 4)

extern __shared__ float smem[];

__global__ __launch_bounds__(512, 1)
void mlp_kernel(const float* __restrict__ data,
                const float* __restrict__ omega,
                const float* __restrict__ eps,
                const float* __restrict__ W1,  const float* __restrict__ b1,
                const float* __restrict__ W2,  const float* __restrict__ b2,
                const float* __restrict__ Wm1, const float* __restrict__ bm1,
                const float* __restrict__ Wm2, const float* __restrict__ bm2,
                const float* __restrict__ Wl1, const float* __restrict__ bl1,
                const float* __restrict__ Wl2, const float* __restrict__ bl2,
                float* __restrict__ out)
{
    float* Hs = smem;                       // 128 x 256
    float* Xs = smem + ROWS * DIM;          // 128 x 16
    float* Ws = Xs + ROWS * BK;             // 16 x 256

    const int tid = threadIdx.x;
    const int tc  = tid & 31;               // column lane (0..31)
    const int tr  = tid >> 5;               // warp id = row group (0..15)
    const int row0 = blockIdx.x * ROWS;

    float acc[8][8];

    // ===================== Stage 1 =====================
    #pragma unroll
    for (int i = 0; i < 8; i++)
        #pragma unroll
        for (int j = 0; j < 8; j++) acc[i][j] = 0.f;

    for (int k0 = 0; k0 < 256; k0 += BK) {
        {
            int r = tid >> 2, q = tid & 3;
            float4 v = *(const float4*)&data[(size_t)(row0 + r) * DIM + k0 + q * 4];
            *(float4*)&Xs[r * BK + q * 4] = v;
        }
        #pragma unroll
        for (int u = 0; u < 2; u++) {
            int idx = tid + u * 512;
            int kk  = idx >> 6;
            int c4  = (idx & 63) * 4;
            *(float4*)&Ws[kk * DIM + c4] =
                *(const float4*)&W1[(size_t)(k0 + kk) * DIM + c4];
        }
        __syncthreads();
        #pragma unroll
        for (int kk = 0; kk < BK; kk++) {
            float a[8], b[8];
            #pragma unroll
            for (int i = 0; i < 8; i++) a[i] = Xs[(tr * 8 + i) * BK + kk];
            #pragma unroll
            for (int j = 0; j < 8; j++) b[j] = Ws[kk * DIM + tc + 32 * j];
            #pragma unroll
            for (int i = 0; i < 8; i++)
                #pragma unroll
                for (int j = 0; j < 8; j++)
                    acc[i][j] = fmaf(a[i], b[j], acc[i][j]);
        }
        __syncthreads();
    }
    {
        float aom[8], bom[8], bb[8];
        #pragma unroll
        for (int i = 0; i < 8; i++) aom[i] = omega[row0 + tr * 8 + i];
        #pragma unroll
        for (int j = 0; j < 8; j++) {
            bom[j] = W1[(size_t)256 * DIM + tc + 32 * j];
            bb[j]  = b1[tc + 32 * j];
        }
        #pragma unroll
        for (int i = 0; i < 8; i++)
            #pragma unroll
            for (int j = 0; j < 8; j++)
                Hs[(tr * 8 + i) * DIM + tc + 32 * j] =
                    fmaxf(fmaf(aom[i], bom[j], acc[i][j]) + bb[j], 0.f);
    }
    __syncthreads();

    // ===================== Stage 2 =====================
    #pragma unroll
    for (int i = 0; i < 8; i++)
        #pragma unroll
        for (int j = 0; j < 8; j++) acc[i][j] = 0.f;

    for (int k0 = 0; k0 < 256; k0 += BK) {
        #pragma unroll
        for (int u = 0; u < 2; u++) {
            int idx = tid + u * 512;
            int kk  = idx >> 6;
            int c4  = (idx & 63) * 4;
            *(float4*)&Ws[kk * DIM + c4] =
                *(const float4*)&W2[(size_t)(k0 + kk) * DIM + c4];
        }
        __syncthreads();
        #pragma unroll
        for (int kk = 0; kk < BK; kk++) {
            float a[8], b[8];
            #pragma unroll
            for (int i = 0; i < 8; i++) a[i] = Hs[(tr * 8 + i) * DIM + k0 + kk];
            #pragma unroll
            for (int j = 0; j < 8; j++) b[j] = Ws[kk * DIM + tc + 32 * j];
            #pragma unroll
            for (int i = 0; i < 8; i++)
                #pragma unroll
                for (int j = 0; j < 8; j++)
                    acc[i][j] = fmaf(a[i], b[j], acc[i][j]);
        }
        __syncthreads();
    }
    {
        float bb[8];
        #pragma unroll
        for (int j = 0; j < 8; j++) bb[j] = b2[tc + 32 * j];
        #pragma unroll
        for (int i = 0; i < 8; i++)
            #pragma unroll
            for (int j = 0; j < 8; j++)
                Hs[(tr * 8 + i) * DIM + tc + 32 * j] =
                    fmaxf(acc[i][j] + bb[j], 0.f);
    }
    __syncthreads();

    // ===================== Stage 3 (two heads) =====================
    #pragma unroll
    for (int i = 0; i < 8; i++)
        #pragma unroll
        for (int j = 0; j < 8; j++) acc[i][j] = 0.f;

    for (int k0 = 0; k0 < 256; k0 += BK) {
        #pragma unroll
        for (int u = 0; u < 2; u++) {
            int idx = tid + u * 512;
            int kk  = idx >> 6;
            int c4  = (idx & 63) * 4;
            const float* src = (c4 < 128)
                ? &Wm1[(size_t)(k0 + kk) * 128 + c4]
                : &Wl1[(size_t)(k0 + kk) * 128 + (c4 - 128)];
            *(float4*)&Ws[kk * DIM + c4] = *(const float4*)src;
        }
        __syncthreads();
        #pragma unroll
        for (int kk = 0; kk < BK; kk++) {
            float a[8], b[8];
            #pragma unroll
            for (int i = 0; i < 8; i++) a[i] = Hs[(tr * 8 + i) * DIM + k0 + kk];
            #pragma unroll
            for (int j = 0; j < 8; j++) b[j] = Ws[kk * DIM + tc + 32 * j];
            #pragma unroll
            for (int i = 0; i < 8; i++)
                #pragma unroll
                for (int j = 0; j < 8; j++)
                    acc[i][j] = fmaf(a[i], b[j], acc[i][j]);
        }
        __syncthreads();
    }
    {
        float bb[8];
        #pragma unroll
        for (int j = 0; j < 8; j++) {
            int c = tc + 32 * j;
            bb[j] = (j < 4) ? bm1[c] : bl1[c - 128];
        }
        #pragma unroll
        for (int i = 0; i < 8; i++)
            #pragma unroll
            for (int j = 0; j < 8; j++)
                Hs[(tr * 8 + i) * DIM + tc + 32 * j] =
                    fmaxf(acc[i][j] + bb[j], 0.f);
    }
    __syncthreads();

    // ===================== Stage 4: head reductions =====================
    const float bm2v = bm2[0];
    const float bl2v = bl2[0];
    #pragma unroll 1
    for (int q = 0; q < 8; q++) {
        int r = tr * 8 + q;
        float s1 = 0.f, s2 = 0.f;
        #pragma unroll
        for (int m = 0; m < 4; m++) {
            int h = tc + 32 * m;
            s1 = fmaf(Hs[r * DIM + h],       __ldg(&Wm2[h]), s1);
            s2 = fmaf(Hs[r * DIM + 128 + h], __ldg(&Wl2[h]), s2);
        }
        #pragma unroll
        for (int o = 16; o > 0; o >>= 1) {
            s1 += __shfl_xor_sync(0xffffffffu, s1, o);
            s2 += __shfl_xor_sync(0xffffffffu, s2, o);
        }
        if (tc == 0) {
            int gr = row0 + r;
            float pm = s1 + bm2v;
            float lv = s2 + bl2v;
            float xm = fmaxf(pm, 0.f) + log1pf(expf(-fabsf(pm)));
            float xi = xm + expf(0.5f * lv) * eps[gr];
            xi = fminf(fmaxf(xi, 0.f), 1.f);
            out[gr]            = xm;   // xi_mean
            out[N_ROWS + gr]   = lv;   // xi_lnvar
            g_xi[gr]           = xi;
        }
    }
}

// ---------------------------------------------------------------------------
// Scan kernel v2: FOUR threads per row; each thread owns 16 hidden units with
// w/v/c all in REGISTERS (no smem/local in the inner loop). Partial sums are
// combined with a 2-level shfl_xor butterfly; all 4 lanes then redundantly
// integrate (y, v). 512 threads/block = 128 rows/block, grid=128 = one wave,
// 16 warps/SM. Output staged 32 steps at a time in smem for coalesced stores.
// ---------------------------------------------------------------------------
#define SRPB 128   // rows per scan block

__global__ __launch_bounds__(512, 1)
void scan_kernel(const float* __restrict__ data,
                 const float* __restrict__ omega,
                 const float* __restrict__ Wa1, const float* __restrict__ ba1,
                 const float* __restrict__ Wa2, const float* __restrict__ ba2,
                 float* __restrict__ out)
{
    __shared__ float ytile[SRPB][33];  // +1 pad: conflict-free write & read

    const int tid = threadIdx.x;
    const int l4  = tid & 3;                   // sub-lane within row group
    const int r   = tid >> 2;                  // local row (0..127)
    const int row = blockIdx.x * SRPB + r;

    // this thread's 16 hidden units: j = l4*16 + i
    float w[16], v[16], c[16];
    const float om = omega[row];
    #pragma unroll
    for (int i = 0; i < 16; i++) {
        int j = l4 * 16 + i;
        w[i] = Wa1[64 + j];                    // W_aux1[1, j]
        v[i] = Wa2[j];                         // W_aux2[j]
        c[i] = fmaf(om, Wa1[j], ba1[j]);       // omega*W_aux1[0,j] + b
    }
    const float b2v = ba2[0];

    float y  = data[(size_t)row * DIM];        // init_y = data[:,0]
    float vv = 0.f;
    const float xi = g_xi[row];                // already clipped to [0,1]
    const float dm = expf(-xi * DT_F);
    float f = 1.f;

    float* __restrict__ xout = out + 2 * N_ROWS;

    for (int t = 0; t < 256; t++) {
        if (l4 == 0) ytile[r][t & 31] = f * y; // x_PAB[row,t]

        float a0 = 0.f, a1 = 0.f, a2 = 0.f, a3 = 0.f;
        #pragma unroll
        for (int i = 0; i < 16; i += 4) {
            a0 = fmaf(fmaxf(fmaf(y, w[i + 0], c[i + 0]), 0.f), v[i + 0], a0);
            a1 = fmaf(fmaxf(fmaf(y, w[i + 1], c[i + 1]), 0.f), v[i + 1], a1);
            a2 = fmaf(fmaxf(fmaf(y, w[i + 2], c[i + 2]), 0.f), v[i + 2], a2);
            a3 = fmaf(fmaxf(fmaf(y, w[i + 3], c[i + 3]), 0.f), v[i + 3], a3);
        }
        float acc = (a0 + a1) + (a2 + a3);
        acc += __shfl_xor_sync(0xffffffffu, acc, 1);
        acc += __shfl_xor_sync(0xffffffffu, acc, 2);
        acc += b2v;

        float ynew = fmaf(DT_F, vv, y);        // y += DT * v   (old v)
        vv = fmaf(DT_F, acc, vv);              // v += DT * acc (acc from old y)
        y  = ynew;
        f *= dm;

        if ((t & 31) == 31) {
            __syncthreads();
            int tb = t - 31;
            #pragma unroll
            for (int i = 0; i < 8; i++) {
                int idx = i * 512 + tid;       // 0..4095 over 128x32 tile
                int rr  = idx >> 5;            // constant per warp
                int cc  = idx & 31;            // = lane -> coalesced
                xout[(size_t)(blockIdx.x * SRPB + rr) * DIM + tb + cc] =
                    ytile[rr][cc];
            }
            __syncthreads();
        }
    }
}

// ---------------------------------------------------------------------------
extern "C" void kernel_launch(void* const* d_in, const int* in_sizes, int n_in,
                              void* d_out, int out_size)
{
    const float* data = (const float*)d_in[0];
    const float* omega= (const float*)d_in[1];
    const float* eps  = (const float*)d_in[2];
    const float* W1   = (const float*)d_in[3];  const float* b1  = (const float*)d_in[4];
    const float* W2   = (const float*)d_in[5];  const float* b2  = (const float*)d_in[6];
    const float* Wm1  = (const float*)d_in[7];  const float* bm1 = (const float*)d_in[8];
    const float* Wm2  = (const float*)d_in[9];  const float* bm2 = (const float*)d_in[10];
    const float* Wl1  = (const float*)d_in[11]; const float* bl1 = (const float*)d_in[12];
    const float* Wl2  = (const float*)d_in[13]; const float* bl2 = (const float*)d_in[14];
    const float* Wa1  = (const float*)d_in[15]; const float* ba1 = (const float*)d_in[16];
    const float* Wa2  = (const float*)d_in[17]; const float* ba2 = (const float*)d_in[18];
    float* out = (float*)d_out;

    cudaFuncSetAttribute(mlp_kernel,
                         cudaFuncAttributeMaxDynamicSharedMemorySize, MLP_SMEM);

    mlp_kernel<<<N_ROWS / ROWS, 512, MLP_SMEM>>>(
        data, omega, eps, W1, b1, W2, b2,
        Wm1, bm1, Wm2, bm2, Wl1, bl1, Wl2, bl2, out);

    scan_kernel<<<N_ROWS / SRPB, 512>>>(data, omega, Wa1, ba1, Wa2, ba2, out);
}

// round 7
// speedup vs baseline: 2.7513x; 1.9641x over previous
#include <cuda_runtime.h>
#include <math.h>
#include <stdint.h>

#define N_ROWS 16384
#define DIM 256
#define DT_F 0.01f

// scratch for xi (clipped), passed from MLP kernel to scan kernel
__device__ float g_xi[N_ROWS];

// ---------------------------------------------------------------------------
// Fused MLP kernel: 128 rows per block, 512 threads, packed f32x2 FFMA.
// Thread (tr, tc): rows tr*8..tr*8+7, column pairs {tc*2 + 64p, +1}, p=0..3.
// Weight tiles software-pipelined: LDG into regs during compute, STS after.
// ---------------------------------------------------------------------------
#define ROWS 128
#define BK   16
#define MLP_SMEM ((ROWS*DIM + ROWS*BK + BK*DIM) * 4)

extern __shared__ float smem[];

typedef unsigned long long u64;

#define FMA2(acc, a2, b2) \
    asm("fma.rn.f32x2 %0, %1, %2, %3;" : "=l"(acc) : "l"(a2), "l"(b2), "l"(acc))

__device__ __forceinline__ u64 dup2(float a) {
    u64 r; uint32_t au = __float_as_uint(a);
    asm("mov.b64 %0, {%1, %1};" : "=l"(r) : "r"(au));
    return r;
}
__device__ __forceinline__ void unpk(u64 x, float& lo, float& hi) {
    uint32_t l, h;
    asm("mov.b64 {%0, %1}, %2;" : "=r"(l), "=r"(h) : "l"(x));
    lo = __uint_as_float(l); hi = __uint_as_float(h);
}

__global__ __launch_bounds__(512, 1)
void mlp_kernel(const float* __restrict__ data,
                const float* __restrict__ omega,
                const float* __restrict__ eps,
                const float* __restrict__ W1,  const float* __restrict__ b1,
                const float* __restrict__ W2,  const float* __restrict__ b2,
                const float* __restrict__ Wm1, const float* __restrict__ bm1,
                const float* __restrict__ Wm2, const float* __restrict__ bm2,
                const float* __restrict__ Wl1, const float* __restrict__ bl1,
                const float* __restrict__ Wl2, const float* __restrict__ bl2,
                float* __restrict__ out)
{
    float* Hs = smem;                       // 128 x 256
    float* Xs = smem + ROWS * DIM;          // 128 x 16
    float* Ws = Xs + ROWS * BK;             // 16 x 256

    const int tid = threadIdx.x;
    const int tc  = tid & 31;               // lane
    const int tr  = tid >> 5;               // warp id = row group (0..15)
    const int row0 = blockIdx.x * ROWS;

    // W-tile prefetch mapping: idx = tid + u*512 (float4 idx), kk = idx>>6, c4 = (idx&63)*4
    const int pf_k0  = tid >> 6;
    const int pf_k1  = (tid + 512) >> 6;
    const int pf_c0  = (tid & 63) * 4;
    // X-tile prefetch mapping (stage 1 only)
    const int px_r = tid >> 2, px_q = tid & 3;

    u64 acc[8][4];
    float4 wreg0, wreg1, xreg;

    // ===================== Stage 1 =====================
    #pragma unroll
    for (int i = 0; i < 8; i++)
        #pragma unroll
        for (int p = 0; p < 4; p++) acc[i][p] = 0ull;

    // prologue: prefetch tile 0
    wreg0 = *(const float4*)&W1[(size_t)pf_k0 * DIM + pf_c0];
    wreg1 = *(const float4*)&W1[(size_t)pf_k1 * DIM + pf_c0];
    xreg  = *(const float4*)&data[(size_t)(row0 + px_r) * DIM + px_q * 4];

    for (int k0 = 0; k0 < 256; k0 += BK) {
        *(float4*)&Ws[pf_k0 * DIM + pf_c0] = wreg0;
        *(float4*)&Ws[pf_k1 * DIM + pf_c0] = wreg1;
        *(float4*)&Xs[px_r * BK + px_q * 4] = xreg;
        __syncthreads();
        if (k0 + BK < 256) {
            wreg0 = *(const float4*)&W1[(size_t)(k0 + BK + pf_k0) * DIM + pf_c0];
            wreg1 = *(const float4*)&W1[(size_t)(k0 + BK + pf_k1) * DIM + pf_c0];
            xreg  = *(const float4*)&data[(size_t)(row0 + px_r) * DIM + k0 + BK + px_q * 4];
        }
        #pragma unroll
        for (int kk = 0; kk < BK; kk++) {
            u64 bq[4];
            #pragma unroll
            for (int p = 0; p < 4; p++)
                bq[p] = *(const u64*)&Ws[kk * DIM + tc * 2 + 64 * p];
            #pragma unroll
            for (int i = 0; i < 8; i++) {
                u64 a2 = dup2(Xs[(tr * 8 + i) * BK + kk]);
                #pragma unroll
                for (int p = 0; p < 4; p++) FMA2(acc[i][p], a2, bq[p]);
            }
        }
        __syncthreads();
    }
    // omega column (k = 256), bias, relu -> Hs
    {
        float aom[8];
        #pragma unroll
        for (int i = 0; i < 8; i++) aom[i] = omega[row0 + tr * 8 + i];
        #pragma unroll
        for (int p = 0; p < 4; p++) {
            int c = tc * 2 + 64 * p;
            float2 bom = *(const float2*)&W1[(size_t)256 * DIM + c];
            float2 bb  = *(const float2*)&b1[c];
            #pragma unroll
            for (int i = 0; i < 8; i++) {
                float lo, hi; unpk(acc[i][p], lo, hi);
                float2 o;
                o.x = fmaxf(fmaf(aom[i], bom.x, lo) + bb.x, 0.f);
                o.y = fmaxf(fmaf(aom[i], bom.y, hi) + bb.y, 0.f);
                *(float2*)&Hs[(tr * 8 + i) * DIM + c] = o;
            }
        }
    }
    __syncthreads();

    // ===================== Stage 2 =====================
    #pragma unroll
    for (int i = 0; i < 8; i++)
        #pragma unroll
        for (int p = 0; p < 4; p++) acc[i][p] = 0ull;

    wreg0 = *(const float4*)&W2[(size_t)pf_k0 * DIM + pf_c0];
    wreg1 = *(const float4*)&W2[(size_t)pf_k1 * DIM + pf_c0];

    for (int k0 = 0; k0 < 256; k0 += BK) {
        *(float4*)&Ws[pf_k0 * DIM + pf_c0] = wreg0;
        *(float4*)&Ws[pf_k1 * DIM + pf_c0] = wreg1;
        __syncthreads();
        if (k0 + BK < 256) {
            wreg0 = *(const float4*)&W2[(size_t)(k0 + BK + pf_k0) * DIM + pf_c0];
            wreg1 = *(const float4*)&W2[(size_t)(k0 + BK + pf_k1) * DIM + pf_c0];
        }
        #pragma unroll
        for (int kk = 0; kk < BK; kk++) {
            u64 bq[4];
            #pragma unroll
            for (int p = 0; p < 4; p++)
                bq[p] = *(const u64*)&Ws[kk * DIM + tc * 2 + 64 * p];
            #pragma unroll
            for (int i = 0; i < 8; i++) {
                u64 a2 = dup2(Hs[(tr * 8 + i) * DIM + k0 + kk]);
                #pragma unroll
                for (int p = 0; p < 4; p++) FMA2(acc[i][p], a2, bq[p]);
            }
        }
        __syncthreads();
    }
    {
        #pragma unroll
        for (int p = 0; p < 4; p++) {
            int c = tc * 2 + 64 * p;
            float2 bb = *(const float2*)&b2[c];
            #pragma unroll
            for (int i = 0; i < 8; i++) {
                float lo, hi; unpk(acc[i][p], lo, hi);
                float2 o;
                o.x = fmaxf(lo + bb.x, 0.f);
                o.y = fmaxf(hi + bb.y, 0.f);
                *(float2*)&Hs[(tr * 8 + i) * DIM + c] = o;
            }
        }
    }
    __syncthreads();

    // ===================== Stage 3 (two heads, 128 cols each) ==============
    #pragma unroll
    for (int i = 0; i < 8; i++)
        #pragma unroll
        for (int p = 0; p < 4; p++) acc[i][p] = 0ull;

    {
        const float* s0 = (pf_c0 < 128) ? &Wm1[(size_t)pf_k0 * 128 + pf_c0]
                                        : &Wl1[(size_t)pf_k0 * 128 + pf_c0 - 128];
        const float* s1 = (pf_c0 < 128) ? &Wm1[(size_t)pf_k1 * 128 + pf_c0]
                                        : &Wl1[(size_t)pf_k1 * 128 + pf_c0 - 128];
        wreg0 = *(const float4*)s0;
        wreg1 = *(const float4*)s1;
    }

    for (int k0 = 0; k0 < 256; k0 += BK) {
        *(float4*)&Ws[pf_k0 * DIM + pf_c0] = wreg0;
        *(float4*)&Ws[pf_k1 * DIM + pf_c0] = wreg1;
        __syncthreads();
        if (k0 + BK < 256) {
            const float* s0 = (pf_c0 < 128)
                ? &Wm1[(size_t)(k0 + BK + pf_k0) * 128 + pf_c0]
                : &Wl1[(size_t)(k0 + BK + pf_k0) * 128 + pf_c0 - 128];
            const float* s1 = (pf_c0 < 128)
                ? &Wm1[(size_t)(k0 + BK + pf_k1) * 128 + pf_c0]
                : &Wl1[(size_t)(k0 + BK + pf_k1) * 128 + pf_c0 - 128];
            wreg0 = *(const float4*)s0;
            wreg1 = *(const float4*)s1;
        }
        #pragma unroll
        for (int kk = 0; kk < BK; kk++) {
            u64 bq[4];
            #pragma unroll
            for (int p = 0; p < 4; p++)
                bq[p] = *(const u64*)&Ws[kk * DIM + tc * 2 + 64 * p];
            #pragma unroll
            for (int i = 0; i < 8; i++) {
                u64 a2 = dup2(Hs[(tr * 8 + i) * DIM + k0 + kk]);
                #pragma unroll
                for (int p = 0; p < 4; p++) FMA2(acc[i][p], a2, bq[p]);
            }
        }
        __syncthreads();
    }
    {
        #pragma unroll
        for (int p = 0; p < 4; p++) {
            int c = tc * 2 + 64 * p;
            float2 bb;
            if (c < 128) bb = *(const float2*)&bm1[c];
            else         bb = *(const float2*)&bl1[c - 128];
            #pragma unroll
            for (int i = 0; i < 8; i++) {
                float lo, hi; unpk(acc[i][p], lo, hi);
                float2 o;
                o.x = fmaxf(lo + bb.x, 0.f);
                o.y = fmaxf(hi + bb.y, 0.f);
                *(float2*)&Hs[(tr * 8 + i) * DIM + c] = o;
            }
        }
    }
    __syncthreads();

    // ===================== Stage 4: head reductions ========================
    const float bm2v = bm2[0];
    const float bl2v = bl2[0];
    #pragma unroll 1
    for (int q = 0; q < 8; q++) {
        int r = tr * 8 + q;
        float s1 = 0.f, s2 = 0.f;
        #pragma unroll
        for (int m = 0; m < 4; m++) {
            int h = tc + 32 * m;
            s1 = fmaf(Hs[r * DIM + h],       __ldg(&Wm2[h]), s1);
            s2 = fmaf(Hs[r * DIM + 128 + h], __ldg(&Wl2[h]), s2);
        }
        #pragma unroll
        for (int o = 16; o > 0; o >>= 1) {
            s1 += __shfl_xor_sync(0xffffffffu, s1, o);
            s2 += __shfl_xor_sync(0xffffffffu, s2, o);
        }
        if (tc == 0) {
            int gr = row0 + r;
            float pm = s1 + bm2v;
            float lv = s2 + bl2v;
            float xm = fmaxf(pm, 0.f) + log1pf(expf(-fabsf(pm)));
            float xi = xm + expf(0.5f * lv) * eps[gr];
            xi = fminf(fmaxf(xi, 0.f), 1.f);
            out[gr]            = xm;   // xi_mean
            out[N_ROWS + gr]   = lv;   // xi_lnvar
            g_xi[gr]           = xi;
        }
    }
}

// ---------------------------------------------------------------------------
// Scan kernel (unchanged from R4): 4 threads/row, all state in registers.
// ---------------------------------------------------------------------------
#define SRPB 128

__global__ __launch_bounds__(512, 1)
void scan_kernel(const float* __restrict__ data,
                 const float* __restrict__ omega,
                 const float* __restrict__ Wa1, const float* __restrict__ ba1,
                 const float* __restrict__ Wa2, const float* __restrict__ ba2,
                 float* __restrict__ out)
{
    __shared__ float ytile[SRPB][33];

    const int tid = threadIdx.x;
    const int l4  = tid & 3;
    const int r   = tid >> 2;
    const int row = blockIdx.x * SRPB + r;

    float w[16], v[16], c[16];
    const float om = omega[row];
    #pragma unroll
    for (int i = 0; i < 16; i++) {
        int j = l4 * 16 + i;
        w[i] = Wa1[64 + j];
        v[i] = Wa2[j];
        c[i] = fmaf(om, Wa1[j], ba1[j]);
    }
    const float b2v = ba2[0];

    float y  = data[(size_t)row * DIM];
    float vv = 0.f;
    const float xi = g_xi[row];
    const float dm = expf(-xi * DT_F);
    float f = 1.f;

    float* __restrict__ xout = out + 2 * N_ROWS;

    for (int t = 0; t < 256; t++) {
        if (l4 == 0) ytile[r][t & 31] = f * y;

        float a0 = 0.f, a1 = 0.f, a2 = 0.f, a3 = 0.f;
        #pragma unroll
        for (int i = 0; i < 16; i += 4) {
            a0 = fmaf(fmaxf(fmaf(y, w[i + 0], c[i + 0]), 0.f), v[i + 0], a0);
            a1 = fmaf(fmaxf(fmaf(y, w[i + 1], c[i + 1]), 0.f), v[i + 1], a1);
            a2 = fmaf(fmaxf(fmaf(y, w[i + 2], c[i + 2]), 0.f), v[i + 2], a2);
            a3 = fmaf(fmaxf(fmaf(y, w[i + 3], c[i + 3]), 0.f), v[i + 3], a3);
        }
        float acc = (a0 + a1) + (a2 + a3);
        acc += __shfl_xor_sync(0xffffffffu, acc, 1);
        acc += __shfl_xor_sync(0xffffffffu, acc, 2);
        acc += b2v;

        float ynew = fmaf(DT_F, vv, y);
        vv = fmaf(DT_F, acc, vv);
        y  = ynew;
        f *= dm;

        if ((t & 31) == 31) {
            __syncthreads();
            int tb = t - 31;
            #pragma unroll
            for (int i = 0; i < 8; i++) {
                int idx = i * 512 + tid;
                int rr  = idx >> 5;
                int cc  = idx & 31;
                xout[(size_t)(blockIdx.x * SRPB + rr) * DIM + tb + cc] =
                    ytile[rr][cc];
            }
            __syncthreads();
        }
    }
}

// ---------------------------------------------------------------------------
extern "C" void kernel_launch(void* const* d_in, const int* in_sizes, int n_in,
                              void* d_out, int out_size)
{
    const float* data = (const float*)d_in[0];
    const float* omega= (const float*)d_in[1];
    const float* eps  = (const float*)d_in[2];
    const float* W1   = (const float*)d_in[3];  const float* b1  = (const float*)d_in[4];
    const float* W2   = (const float*)d_in[5];  const float* b2  = (const float*)d_in[6];
    const float* Wm1  = (const float*)d_in[7];  const float* bm1 = (const float*)d_in[8];
    const float* Wm2  = (const float*)d_in[9];  const float* bm2 = (const float*)d_in[10];
    const float* Wl1  = (const float*)d_in[11]; const float* bl1 = (const float*)d_in[12];
    const float* Wl2  = (const float*)d_in[13]; const float* bl2 = (const float*)d_in[14];
    const float* Wa1  = (const float*)d_in[15]; const float* ba1 = (const float*)d_in[16];
    const float* Wa2  = (const float*)d_in[17]; const float* ba2 = (const float*)d_in[18];
    float* out = (float*)d_out;

    cudaFuncSetAttribute(mlp_kernel,
                         cudaFuncAttributeMaxDynamicSharedMemorySize, MLP_SMEM);

    mlp_kernel<<<N_ROWS / ROWS, 512, MLP_SMEM>>>(
        data, omega, eps, W1, b1, W2, b2,
        Wm1, bm1, Wm2, bm2, Wl1, bl1, Wl2, bl2, out);

    scan_kernel<<<N_ROWS / SRPB, 512>>>(data, omega, Wa1, ba1, Wa2, ba2, out);
}